// round 8
// baseline (speedup 1.0000x reference)
#include <cuda_runtime.h>
#include <math.h>
#include <cstdint>

#define SEQ      32000
#define NF       80
#define KF       128       // folded K: 126 real + 2 zero pad
#define MP       128       // positions per tile
#define TPB      8         // tiles per block
#define GRID     1000      // GRID*TPB = 8000 = 32 batches * 250 jtiles
#define NTHREADS 320       // 10 warps = 2 pos-halves x 5 filter stripes

// Folded filters, bf16 hi/lo splits, as u32 k-pairs: [split][o][kpair 0..63]
__device__ uint32_t g_Ff[2 * NF * (KF / 2)];

// smem: double-buffered P hi/lo. Row stride 272 B -> conflict-free A-frag
// loads (bank = 4*(row%8) + (lane%4), all 32 distinct).
#define PS      272
#define PBUF    (MP * PS)              // 34816 B (one split)
#define BUFSZ   (2 * PBUF)             // Ph + Pl per buffer
#define SMEM_TOTAL (2 * BUFSZ)         // 139264 B

#define MMA_BF16(d, a, bb)                                                  \
    asm volatile("mma.sync.aligned.m16n8k16.row.col.f32.bf16.bf16.f32 "     \
        "{%0,%1,%2,%3}, {%4,%5,%6,%7}, {%8,%9}, {%0,%1,%2,%3};"             \
        : "+f"((d)[0]), "+f"((d)[1]), "+f"((d)[2]), "+f"((d)[3])            \
        : "r"((a)[0]), "r"((a)[1]), "r"((a)[2]), "r"((a)[3]),               \
          "r"((bb)[0]), "r"((bb)[1]))

// ---------------------------------------------------------------------------
// Kernel A: build folded filters (center tap pre-halved), split to bf16
// hi/lo, store as u32 k-pairs. One block per filter, 128 threads.
// sin/cos in double of the fp32-rounded argument (fast-math immune).
// ---------------------------------------------------------------------------
__global__ void gen_filters_kernel(const float* __restrict__ fb1,
                                   const float* __restrict__ fband) {
    const int o = blockIdx.x;
    const int k = threadIdx.x;          // tap 0..125 (125 = center); 126..127 pad
    const float two_pi = 6.2831853071795864769f;
    const float fs = 16000.0f;
    const float minf = 50.0f / fs;
    const float beg = fabsf(fb1[o]) + minf;
    const float end = beg + fabsf(fband[o]) + minf;

    float val = 0.0f;
    float bpv = -3.0e38f;
    if (k < 126) {
        const int ti = 125 - k;
        if (ti == 0) {
            val = 2.0f * end - 2.0f * beg;
        } else {
            const float t  = (float)ti;
            const float ae = (two_pi * (end * fs)) * t;
            const float ab = (two_pi * (beg * fs)) * t;
            val = (2.0f * end) * ((float)sin((double)ae) / ae)
                - (2.0f * beg) * ((float)sin((double)ab) / ab);
        }
        bpv = val;
    }
    __shared__ float red[128];
    red[threadIdx.x] = bpv;
    __syncthreads();
    for (int s = 64; s > 0; s >>= 1) {
        if (threadIdx.x < s)
            red[threadIdx.x] = fmaxf(red[threadIdx.x], red[threadIdx.x + s]);
        __syncthreads();
    }
    const float mx = red[0];

    float fv = 0.0f;
    if (k < 126) {
        const float nk  = (float)k * (251.0f / 250.0f);
        const float wa  = (two_pi * nk) / 251.0f;
        const float win = 0.54f - 0.46f * (float)cos((double)wa);
        fv = (val / mx) * win;
        if (k == 125) fv *= 0.5f;       // center: P doubles it back
    }
    uint32_t hb, lb;
    asm("cvt.rn.bf16x2.f32 %0, %1, %2;" : "=r"(hb) : "f"(0.0f), "f"(fv));
    const float hi  = __uint_as_float(hb << 16);
    const float res = fv - hi;
    asm("cvt.rn.bf16x2.f32 %0, %1, %2;" : "=r"(lb) : "f"(0.0f), "f"(res));

    unsigned short* F16 = (unsigned short*)g_Ff;
    F16[o * KF + k]            = (unsigned short)(hb & 0xffffu);
    F16[(NF + o) * KF + k]     = (unsigned short)(lb & 0xffffu);
}

// ---------------------------------------------------------------------------
// Kernel B: folded conv as 3-term bf16-split HMMA GEMM, software-pipelined:
// build(it+1) (LDG from L1-resident x, CVT, STS into buffer nb) is issued
// before mma(it) (LDS + HMMA from buffer cb); ONE barrier per tile.
// Warp w: pos-half h=w/5 (64 rows), filter stripe s=w%5 (16 cols).
// B-fragments (filters) resident in registers across all TPB tiles.
// ---------------------------------------------------------------------------
extern __shared__ char smem[];

__global__ void __launch_bounds__(NTHREADS, 1)
conv_kernel(const float* __restrict__ x, float* __restrict__ out) {
    const int tid  = threadIdx.x;
    const int lane = tid & 31;
    const int warp = tid >> 5;
    const int h    = warp / 5;          // 0..1 position half
    const int s    = warp % 5;          // 0..4 filter stripe
    const int ln4  = lane >> 2;         // 0..7
    const int lm4  = lane & 3;          // 0..3

    // ---- load B fragments once: [split][ntile][kstep][reg] ----
    uint32_t bf[2][2][8][2];
#pragma unroll
    for (int sp = 0; sp < 2; ++sp)
#pragma unroll
        for (int nt = 0; nt < 2; ++nt)
#pragma unroll
            for (int ks = 0; ks < 8; ++ks) {
                const int n = s * 16 + nt * 8 + ln4;
                const uint32_t* Fp = g_Ff + (sp * NF + n) * (KF / 2) + ks * 8 + lm4;
                bf[sp][nt][ks][0] = Fp[0];
                bf[sp][nt][ks][1] = Fp[4];
            }

    // ---- build P(t) into buffer buf: P[j][k] = x[j+k] + x[j+250-k] ----
    auto build = [&](int t, int buf) {
        const int b  = t / 250;
        const int J0 = (t % 250) * MP;
        const float* xb = x + (size_t)b * SEQ + (J0 - 125);
        char* PhB = smem + buf * BUFSZ;
        char* PlB = PhB + PBUF;
        const bool interior = (J0 >= 125) && (J0 + 253 <= SEQ);
        for (int idx = tid; idx < MP * 64; idx += NTHREADS) {
            const int j  = idx >> 6;
            const int kp = idx & 63;
            const int k  = kp * 2;
            float p0 = 0.0f, p1 = 0.0f;
            if (kp < 63) {
                if (interior) {
                    p0 = __ldg(xb + j + k)     + __ldg(xb + j + 250 - k);
                    p1 = __ldg(xb + j + k + 1) + __ldg(xb + j + 249 - k);
                } else {
                    const int g0 = J0 - 125 + j + k;
                    const int g2 = J0 + 125 + j - k;
                    const float a0 = (g0 >= 0     && g0 < SEQ)     ? __ldg(xb + j + k)       : 0.0f;
                    const float a1 = (g0 + 1 >= 0 && g0 + 1 < SEQ) ? __ldg(xb + j + k + 1)   : 0.0f;
                    const float a2 = (g2 >= 0     && g2 < SEQ)     ? __ldg(xb + j + 250 - k) : 0.0f;
                    const float a3 = (g2 - 1 >= 0 && g2 - 1 < SEQ) ? __ldg(xb + j + 249 - k) : 0.0f;
                    p0 = a0 + a2;
                    p1 = a1 + a3;
                }
            }
            uint32_t hp;
            asm("cvt.rn.bf16x2.f32 %0, %1, %2;" : "=r"(hp) : "f"(p1), "f"(p0));
            const float h0 = __uint_as_float(hp << 16);
            const float h1 = __uint_as_float(hp & 0xffff0000u);
            const float r0 = p0 - h0, r1 = p1 - h1;
            uint32_t lp;
            asm("cvt.rn.bf16x2.f32 %0, %1, %2;" : "=r"(lp) : "f"(r1), "f"(r0));
            *(uint32_t*)(PhB + j * PS + kp * 4) = hp;
            *(uint32_t*)(PlB + j * PS + kp * 4) = lp;
        }
    };

    // prologue: build tile 0
    build(blockIdx.x * TPB, 0);
    __syncthreads();

    for (int it = 0; it < TPB; ++it) {
        const int t   = blockIdx.x * TPB + it;
        const int b   = t / 250;
        const int J0  = (t % 250) * MP;
        const int cb  = it & 1;

        // pipeline: issue next tile's build first (LDG/CVT/STS — disjoint
        // pipes from the HMMA stream below; warps desync across the mix)
        if (it + 1 < TPB) build(t + 1, cb ^ 1);

        // ---- mma(it): 4 m-tiles x 2 n-tiles x 8 k-steps x 3 terms ----
        char* Ph = smem + cb * BUFSZ;
        char* Pl = Ph + PBUF;

        float acc[4][2][4];
#pragma unroll
        for (int mt = 0; mt < 4; ++mt)
#pragma unroll
            for (int nt = 0; nt < 2; ++nt)
#pragma unroll
                for (int r = 0; r < 4; ++r) acc[mt][nt][r] = 0.0f;

        const int rbase = h * 64 + ln4;
#pragma unroll
        for (int ks = 0; ks < 8; ++ks) {
            uint32_t ah[4][4], al[4][4];
#pragma unroll
            for (int mt = 0; mt < 4; ++mt) {
                const int row = rbase + mt * 16;
                const char* ph = Ph + row * PS + ks * 32 + lm4 * 4;
                const char* pl = Pl + row * PS + ks * 32 + lm4 * 4;
                ah[mt][0] = *(const uint32_t*)(ph);
                ah[mt][1] = *(const uint32_t*)(ph + 8 * PS);
                ah[mt][2] = *(const uint32_t*)(ph + 16);
                ah[mt][3] = *(const uint32_t*)(ph + 8 * PS + 16);
                al[mt][0] = *(const uint32_t*)(pl);
                al[mt][1] = *(const uint32_t*)(pl + 8 * PS);
                al[mt][2] = *(const uint32_t*)(pl + 16);
                al[mt][3] = *(const uint32_t*)(pl + 8 * PS + 16);
            }
#pragma unroll
            for (int mt = 0; mt < 4; ++mt)
#pragma unroll
                for (int nt = 0; nt < 2; ++nt) {
                    MMA_BF16(acc[mt][nt], ah[mt], bf[0][nt][ks]);  // Ph*Fh
                    MMA_BF16(acc[mt][nt], al[mt], bf[0][nt][ks]);  // Pl*Fh
                    MMA_BF16(acc[mt][nt], ah[mt], bf[1][nt][ks]);  // Ph*Fl
                }
        }

        // ---- epilogue: c0(r,o) c1(r,o+1) c2(r+8,o) c3(r+8,o+1) ----
#pragma unroll
        for (int mt = 0; mt < 4; ++mt) {
            const int rr = rbase + mt * 16;
#pragma unroll
            for (int nt = 0; nt < 2; ++nt) {
                const int o = s * 16 + nt * 8 + lm4 * 2;
                float* op = out + ((size_t)b * NF + o) * SEQ + J0;
                op[rr]           = acc[mt][nt][0];
                op[SEQ + rr]     = acc[mt][nt][1];
                op[rr + 8]       = acc[mt][nt][2];
                op[SEQ + rr + 8] = acc[mt][nt][3];
            }
        }

        __syncthreads();    // nb fully built + cb fully consumed everywhere
    }
}

// ---------------------------------------------------------------------------
extern "C" void kernel_launch(void* const* d_in, const int* in_sizes, int n_in,
                              void* d_out, int out_size) {
    const float* x     = (const float*)d_in[0];
    const float* fb1   = (const float*)d_in[1];
    const float* fband = (const float*)d_in[2];
    float* out = (float*)d_out;

    cudaFuncSetAttribute(conv_kernel,
                         cudaFuncAttributeMaxDynamicSharedMemorySize, SMEM_TOTAL);

    gen_filters_kernel<<<NF, 128>>>(fb1, fband);
    conv_kernel<<<GRID, NTHREADS, SMEM_TOTAL>>>(x, out);
}

// round 10
// speedup vs baseline: 1.3249x; 1.3249x over previous
#include <cuda_runtime.h>
#include <math.h>
#include <cstdint>

#define SEQ      32000
#define NF       80
#define KF       128       // folded K: 126 real + 2 zero pad
#define MP       64        // positions per tile
#define JT       500       // jtiles per batch = SEQ/MP
#define TPB      16        // tiles per block
#define GRID     1000      // GRID*TPB = 16000 = 32 batches * 500 jtiles
#define NTHREADS 160       // 5 warps = 5 filter stripes; 2 CTAs/SM

// Folded filters, bf16 hi/lo splits, as u32 k-pairs: [split][o][kpair 0..63]
__device__ uint32_t g_Ff[2 * NF * (KF / 2)];

// smem: x window + P hi/lo. P row stride 272 B -> conflict-free A-frag
// loads (bank = 4*(row%8) + (lane%4), all 32 distinct).
#define PS      272
#define XW_OFF  0                       // 320 floats (314 used)
#define PH_OFF  1280
#define PL_OFF  (PH_OFF + MP * PS)      // + 17408
#define SMEM_TOTAL (PL_OFF + MP * PS)   // 36096 B -> 2 CTAs/SM

#define MMA_BF16(d, a, bb)                                                  \
    asm volatile("mma.sync.aligned.m16n8k16.row.col.f32.bf16.bf16.f32 "     \
        "{%0,%1,%2,%3}, {%4,%5,%6,%7}, {%8,%9}, {%0,%1,%2,%3};"             \
        : "+f"((d)[0]), "+f"((d)[1]), "+f"((d)[2]), "+f"((d)[3])            \
        : "r"((a)[0]), "r"((a)[1]), "r"((a)[2]), "r"((a)[3]),               \
          "r"((bb)[0]), "r"((bb)[1]))

// ---------------------------------------------------------------------------
// Kernel A: build folded filters (center tap pre-halved), split to bf16
// hi/lo, store as u32 k-pairs. One block per filter, 128 threads.
// sin/cos in double of the fp32-rounded argument (fast-math immune).
// ---------------------------------------------------------------------------
__global__ void gen_filters_kernel(const float* __restrict__ fb1,
                                   const float* __restrict__ fband) {
    const int o = blockIdx.x;
    const int k = threadIdx.x;          // tap 0..125 (125 = center); 126..127 pad
    const float two_pi = 6.2831853071795864769f;
    const float fs = 16000.0f;
    const float minf = 50.0f / fs;
    const float beg = fabsf(fb1[o]) + minf;
    const float end = beg + fabsf(fband[o]) + minf;

    float val = 0.0f;
    float bpv = -3.0e38f;
    if (k < 126) {
        const int ti = 125 - k;
        if (ti == 0) {
            val = 2.0f * end - 2.0f * beg;
        } else {
            const float t  = (float)ti;
            const float ae = (two_pi * (end * fs)) * t;
            const float ab = (two_pi * (beg * fs)) * t;
            val = (2.0f * end) * ((float)sin((double)ae) / ae)
                - (2.0f * beg) * ((float)sin((double)ab) / ab);
        }
        bpv = val;
    }
    __shared__ float red[128];
    red[threadIdx.x] = bpv;
    __syncthreads();
    for (int s = 64; s > 0; s >>= 1) {
        if (threadIdx.x < s)
            red[threadIdx.x] = fmaxf(red[threadIdx.x], red[threadIdx.x + s]);
        __syncthreads();
    }
    const float mx = red[0];

    float fv = 0.0f;
    if (k < 126) {
        const float nk  = (float)k * (251.0f / 250.0f);
        const float wa  = (two_pi * nk) / 251.0f;
        const float win = 0.54f - 0.46f * (float)cos((double)wa);
        fv = (val / mx) * win;
        if (k == 125) fv *= 0.5f;       // center: P doubles it back
    }
    uint32_t hb, lb;
    asm("cvt.rn.bf16x2.f32 %0, %1, %2;" : "=r"(hb) : "f"(0.0f), "f"(fv));
    const float hi  = __uint_as_float(hb << 16);
    const float res = fv - hi;
    asm("cvt.rn.bf16x2.f32 %0, %1, %2;" : "=r"(lb) : "f"(0.0f), "f"(res));

    unsigned short* F16 = (unsigned short*)g_Ff;
    F16[o * KF + k]            = (unsigned short)(hb & 0xffffu);
    F16[(NF + o) * KF + k]     = (unsigned short)(lb & 0xffffu);
}

// ---------------------------------------------------------------------------
// Kernel B: folded conv as 3-term bf16-split HMMA GEMM.
// Per tile: D[64 pos, 80 filt] = Ph*Fh + Pl*Fh + Ph*Fl.
// CTA = 5 warps, warp = filter stripe (16 filters), all 64 positions.
// 2 CTAs/SM: independent CTAs interleave build (l1tex) and mma (tensor)
// phases — the overlap in-order warps cannot provide intra-CTA.
// B-fragments (filters) resident in registers across all TPB tiles.
// ---------------------------------------------------------------------------
extern __shared__ char smem[];

__global__ void __launch_bounds__(NTHREADS, 2)
conv_kernel(const float* __restrict__ x, float* __restrict__ out) {
    float* xw = (float*)(smem + XW_OFF);
    char*  Ph = smem + PH_OFF;
    char*  Pl = smem + PL_OFF;

    const int tid  = threadIdx.x;
    const int lane = tid & 31;
    const int s    = tid >> 5;          // 0..4 filter stripe
    const int ln4  = lane >> 2;         // 0..7
    const int lm4  = lane & 3;          // 0..3

    // ---- load B fragments once: [split][ntile][kstep][reg] ----
    uint32_t bf[2][2][8][2];
#pragma unroll
    for (int sp = 0; sp < 2; ++sp)
#pragma unroll
        for (int nt = 0; nt < 2; ++nt)
#pragma unroll
            for (int ks = 0; ks < 8; ++ks) {
                const int n = s * 16 + nt * 8 + ln4;
                const uint32_t* Fp = g_Ff + (sp * NF + n) * (KF / 2) + ks * 8 + lm4;
                bf[sp][nt][ks][0] = Fp[0];
                bf[sp][nt][ks][1] = Fp[4];
            }

    for (int it = 0; it < TPB; ++it) {
        const int t  = blockIdx.x * TPB + it;
        const int b  = t / JT;
        const int J0 = (t % JT) * MP;

        __syncthreads();            // previous tile's P/xw fully consumed

        // 1) stage raw x window [J0-125, J0+189)
        const float* xb = x + (size_t)b * SEQ;
        for (int q = tid; q < MP + 250; q += NTHREADS) {
            const int g = J0 - 125 + q;
            xw[q] = (g >= 0 && g < SEQ) ? xb[g] : 0.0f;
        }
        __syncthreads();

        // 2) build P hi/lo: P[j][k] = x[j+k] + x[j+250-k], k-pairs packed
        for (int idx = tid; idx < MP * 64; idx += NTHREADS) {
            const int j  = idx >> 6;
            const int kp = idx & 63;
            const int k  = kp * 2;
            float p0 = 0.0f, p1 = 0.0f;
            if (kp < 63) {
                p0 = xw[j + k]     + xw[j + 250 - k];
                p1 = xw[j + k + 1] + xw[j + 249 - k];
            }
            uint32_t hp;
            asm("cvt.rn.bf16x2.f32 %0, %1, %2;" : "=r"(hp) : "f"(p1), "f"(p0));
            const float h0 = __uint_as_float(hp << 16);
            const float h1 = __uint_as_float(hp & 0xffff0000u);
            const float r0 = p0 - h0, r1 = p1 - h1;
            uint32_t lp;
            asm("cvt.rn.bf16x2.f32 %0, %1, %2;" : "=r"(lp) : "f"(r1), "f"(r0));
            *(uint32_t*)(Ph + j * PS + kp * 4) = hp;
            *(uint32_t*)(Pl + j * PS + kp * 4) = lp;
        }
        __syncthreads();

        // 3) HMMA mainloop: 4 m-tiles x 2 n-tiles x 8 k-steps x 3 terms
        float acc[4][2][4];
#pragma unroll
        for (int mt = 0; mt < 4; ++mt)
#pragma unroll
            for (int nt = 0; nt < 2; ++nt)
#pragma unroll
                for (int r = 0; r < 4; ++r) acc[mt][nt][r] = 0.0f;

#pragma unroll
        for (int ks = 0; ks < 8; ++ks) {
            uint32_t ah[4][4], al[4][4];
#pragma unroll
            for (int mt = 0; mt < 4; ++mt) {
                const int row = ln4 + mt * 16;
                const char* ph = Ph + row * PS + ks * 32 + lm4 * 4;
                const char* pl = Pl + row * PS + ks * 32 + lm4 * 4;
                ah[mt][0] = *(const uint32_t*)(ph);
                ah[mt][1] = *(const uint32_t*)(ph + 8 * PS);
                ah[mt][2] = *(const uint32_t*)(ph + 16);
                ah[mt][3] = *(const uint32_t*)(ph + 8 * PS + 16);
                al[mt][0] = *(const uint32_t*)(pl);
                al[mt][1] = *(const uint32_t*)(pl + 8 * PS);
                al[mt][2] = *(const uint32_t*)(pl + 16);
                al[mt][3] = *(const uint32_t*)(pl + 8 * PS + 16);
            }
#pragma unroll
            for (int mt = 0; mt < 4; ++mt)
#pragma unroll
                for (int nt = 0; nt < 2; ++nt) {
                    MMA_BF16(acc[mt][nt], ah[mt], bf[0][nt][ks]);  // Ph*Fh
                    MMA_BF16(acc[mt][nt], al[mt], bf[0][nt][ks]);  // Pl*Fh
                    MMA_BF16(acc[mt][nt], ah[mt], bf[1][nt][ks]);  // Ph*Fl
                }
        }

        // 4) epilogue: c0(r,o) c1(r,o+1) c2(r+8,o) c3(r+8,o+1)
#pragma unroll
        for (int mt = 0; mt < 4; ++mt) {
            const int rr = ln4 + mt * 16;
#pragma unroll
            for (int nt = 0; nt < 2; ++nt) {
                const int o = s * 16 + nt * 8 + lm4 * 2;
                float* op = out + ((size_t)b * NF + o) * SEQ + J0;
                op[rr]           = acc[mt][nt][0];
                op[SEQ + rr]     = acc[mt][nt][1];
                op[rr + 8]       = acc[mt][nt][2];
                op[SEQ + rr + 8] = acc[mt][nt][3];
            }
        }
    }
}

// ---------------------------------------------------------------------------
extern "C" void kernel_launch(void* const* d_in, const int* in_sizes, int n_in,
                              void* d_out, int out_size) {
    const float* x     = (const float*)d_in[0];
    const float* fb1   = (const float*)d_in[1];
    const float* fband = (const float*)d_in[2];
    float* out = (float*)d_out;

    cudaFuncSetAttribute(conv_kernel,
                         cudaFuncAttributeMaxDynamicSharedMemorySize, SMEM_TOTAL);

    gen_filters_kernel<<<NF, 128>>>(fb1, fband);
    conv_kernel<<<GRID, NTHREADS, SMEM_TOTAL>>>(x, out);
}

// round 12
// speedup vs baseline: 1.3413x; 1.0124x over previous
#include <cuda_runtime.h>
#include <math.h>
#include <cstdint>

#define SEQ      32000
#define NF       80
#define KF       128       // folded K: 126 real + 2 zero pad
#define MP       64        // positions per tile
#define JT       500       // jtiles per batch = SEQ/MP
#define TPB      16        // tiles per block
#define GRID     1000      // GRID*TPB = 16000 = 32 batches * 500 jtiles
#define NTHREADS 160       // 5 warps = 5 filter stripes; 2 CTAs/SM

// Folded filters, bf16 hi/lo splits, as u32 k-pairs: [split][o][kpair 0..63]
__device__ uint32_t g_Ff[2 * NF * (KF / 2)];

// smem: x window + P hi/lo. P row stride 272 B -> conflict-free LDSM phases
// (row byte offset 272*r => bank 4r..4r+3, all 32 distinct per phase).
#define PS      272
#define XW_OFF  0                       // 320 floats (314 used)
#define PH_OFF  1280
#define PL_OFF  (PH_OFF + MP * PS)      // + 17408
#define SMEM_TOTAL (PL_OFF + MP * PS)   // 36096 B -> 2 CTAs/SM

#define MMA_BF16(d, a, bb)                                                  \
    asm volatile("mma.sync.aligned.m16n8k16.row.col.f32.bf16.bf16.f32 "     \
        "{%0,%1,%2,%3}, {%4,%5,%6,%7}, {%8,%9}, {%0,%1,%2,%3};"             \
        : "+f"((d)[0]), "+f"((d)[1]), "+f"((d)[2]), "+f"((d)[3])            \
        : "r"((a)[0]), "r"((a)[1]), "r"((a)[2]), "r"((a)[3]),               \
          "r"((bb)[0]), "r"((bb)[1]))

#define LDSM_X4(r, addr)                                                    \
    asm volatile("ldmatrix.sync.aligned.m8n8.x4.shared.b16 {%0,%1,%2,%3}, [%4];" \
        : "=r"((r)[0]), "=r"((r)[1]), "=r"((r)[2]), "=r"((r)[3])            \
        : "r"(addr))

// ---------------------------------------------------------------------------
// Kernel A: build folded filters (center tap pre-halved), split to bf16
// hi/lo, store as u32 k-pairs. One block per filter, 128 threads.
// sin/cos in double of the fp32-rounded argument (fast-math immune).
// ---------------------------------------------------------------------------
__global__ void gen_filters_kernel(const float* __restrict__ fb1,
                                   const float* __restrict__ fband) {
    const int o = blockIdx.x;
    const int k = threadIdx.x;          // tap 0..125 (125 = center); 126..127 pad
    const float two_pi = 6.2831853071795864769f;
    const float fs = 16000.0f;
    const float minf = 50.0f / fs;
    const float beg = fabsf(fb1[o]) + minf;
    const float end = beg + fabsf(fband[o]) + minf;

    float val = 0.0f;
    float bpv = -3.0e38f;
    if (k < 126) {
        const int ti = 125 - k;
        if (ti == 0) {
            val = 2.0f * end - 2.0f * beg;
        } else {
            const float t  = (float)ti;
            const float ae = (two_pi * (end * fs)) * t;
            const float ab = (two_pi * (beg * fs)) * t;
            val = (2.0f * end) * ((float)sin((double)ae) / ae)
                - (2.0f * beg) * ((float)sin((double)ab) / ab);
        }
        bpv = val;
    }
    __shared__ float red[128];
    red[threadIdx.x] = bpv;
    __syncthreads();
    for (int s = 64; s > 0; s >>= 1) {
        if (threadIdx.x < s)
            red[threadIdx.x] = fmaxf(red[threadIdx.x], red[threadIdx.x + s]);
        __syncthreads();
    }
    const float mx = red[0];

    float fv = 0.0f;
    if (k < 126) {
        const float nk  = (float)k * (251.0f / 250.0f);
        const float wa  = (two_pi * nk) / 251.0f;
        const float win = 0.54f - 0.46f * (float)cos((double)wa);
        fv = (val / mx) * win;
        if (k == 125) fv *= 0.5f;       // center: P doubles it back
    }
    uint32_t hb, lb;
    asm("cvt.rn.bf16x2.f32 %0, %1, %2;" : "=r"(hb) : "f"(0.0f), "f"(fv));
    const float hi  = __uint_as_float(hb << 16);
    const float res = fv - hi;
    asm("cvt.rn.bf16x2.f32 %0, %1, %2;" : "=r"(lb) : "f"(0.0f), "f"(res));

    unsigned short* F16 = (unsigned short*)g_Ff;
    F16[o * KF + k]            = (unsigned short)(hb & 0xffffu);
    F16[(NF + o) * KF + k]     = (unsigned short)(lb & 0xffffu);
}

// ---------------------------------------------------------------------------
// Kernel B: folded conv as 3-term bf16-split HMMA GEMM.
// Per tile: D[64 pos, 80 filt] = Ph*Fh + Pl*Fh + Ph*Fl.
// CTA = 5 warps (one 16-filter stripe each), 2 CTAs/SM.
// A-fragments via ldmatrix.x4 (4x fewer issue slots, shorter dep chains).
// B-fragments (both splits) register-resident across all TPB tiles.
// ---------------------------------------------------------------------------
extern __shared__ char smem[];

__global__ void __launch_bounds__(NTHREADS, 2)
conv_kernel(const float* __restrict__ x, float* __restrict__ out) {
    float* xw = (float*)(smem + XW_OFF);
    char*  Ph = smem + PH_OFF;
    char*  Pl = smem + PL_OFF;

    const int tid  = threadIdx.x;
    const int lane = tid & 31;
    const int s    = tid >> 5;          // 0..4 filter stripe
    const int ln4  = lane >> 2;         // 0..7
    const int lm4  = lane & 3;          // 0..3

    // ---- load B fragments once: [split][ntile][kstep][reg] ----
    uint32_t bf[2][2][8][2];
#pragma unroll
    for (int sp = 0; sp < 2; ++sp)
#pragma unroll
        for (int nt = 0; nt < 2; ++nt)
#pragma unroll
            for (int ks = 0; ks < 8; ++ks) {
                const int n = s * 16 + nt * 8 + ln4;
                const uint32_t* Fp = g_Ff + (sp * NF + n) * (KF / 2) + ks * 8 + lm4;
                bf[sp][nt][ks][0] = Fp[0];
                bf[sp][nt][ks][1] = Fp[4];
            }

    // ldmatrix lane base: rows (lane&15), matrices 2,3 at +16 bytes
    uint32_t sbu;
    asm("{ .reg .u64 t; cvta.to.shared.u64 t, %1; cvt.u32.u64 %0, t; }"
        : "=r"(sbu) : "l"(smem));
    const uint32_t aAddr = sbu + PH_OFF + (uint32_t)((lane & 15) * PS)
                         + (uint32_t)((lane >> 4) * 16);

    for (int it = 0; it < TPB; ++it) {
        const int t  = blockIdx.x * TPB + it;
        const int b  = t / JT;
        const int J0 = (t % JT) * MP;

        __syncthreads();            // previous tile's P/xw fully consumed

        // 1) stage raw x window [J0-125, J0+189)
        const float* xb = x + (size_t)b * SEQ;
        for (int q = tid; q < MP + 250; q += NTHREADS) {
            const int g = J0 - 125 + q;
            xw[q] = (g >= 0 && g < SEQ) ? xb[g] : 0.0f;
        }
        __syncthreads();

        // 2) build P hi/lo: P[j][k] = x[j+k] + x[j+250-k], k-pairs packed
        for (int idx = tid; idx < MP * 64; idx += NTHREADS) {
            const int j  = idx >> 6;
            const int kp = idx & 63;
            const int k  = kp * 2;
            float p0 = 0.0f, p1 = 0.0f;
            if (kp < 63) {
                p0 = xw[j + k]     + xw[j + 250 - k];
                p1 = xw[j + k + 1] + xw[j + 249 - k];
            }
            uint32_t hp;
            asm("cvt.rn.bf16x2.f32 %0, %1, %2;" : "=r"(hp) : "f"(p1), "f"(p0));
            const float h0 = __uint_as_float(hp << 16);
            const float h1 = __uint_as_float(hp & 0xffff0000u);
            const float r0 = p0 - h0, r1 = p1 - h1;
            uint32_t lp;
            asm("cvt.rn.bf16x2.f32 %0, %1, %2;" : "=r"(lp) : "f"(r1), "f"(r0));
            *(uint32_t*)(Ph + j * PS + kp * 4) = hp;
            *(uint32_t*)(Pl + j * PS + kp * 4) = lp;
        }
        __syncthreads();

        // 3) HMMA mainloop: 4 m-tiles x 2 n-tiles x 8 k-steps x 3 terms
        float acc[4][2][4];
#pragma unroll
        for (int mt = 0; mt < 4; ++mt)
#pragma unroll
            for (int nt = 0; nt < 2; ++nt)
#pragma unroll
                for (int r = 0; r < 4; ++r) acc[mt][nt][r] = 0.0f;

#pragma unroll
        for (int ks = 0; ks < 8; ++ks) {
            uint32_t ah[4][4], al[4][4];
#pragma unroll
            for (int mt = 0; mt < 4; ++mt) {
                const uint32_t a0 = aAddr + (uint32_t)(mt * 16 * PS + ks * 32);
                LDSM_X4(ah[mt], a0);
                LDSM_X4(al[mt], a0 + (uint32_t)(PL_OFF - PH_OFF));
            }
#pragma unroll
            for (int mt = 0; mt < 4; ++mt)
#pragma unroll
                for (int nt = 0; nt < 2; ++nt) {
                    MMA_BF16(acc[mt][nt], ah[mt], bf[0][nt][ks]);  // Ph*Fh
                    MMA_BF16(acc[mt][nt], al[mt], bf[0][nt][ks]);  // Pl*Fh
                    MMA_BF16(acc[mt][nt], ah[mt], bf[1][nt][ks]);  // Ph*Fl
                }
        }

        // 4) epilogue: c0(r,o) c1(r,o+1) c2(r+8,o) c3(r+8,o+1)
#pragma unroll
        for (int mt = 0; mt < 4; ++mt) {
            const int rr = ln4 + mt * 16;
#pragma unroll
            for (int nt = 0; nt < 2; ++nt) {
                const int o = s * 16 + nt * 8 + lm4 * 2;
                float* op = out + ((size_t)b * NF + o) * SEQ + J0;
                op[rr]           = acc[mt][nt][0];
                op[SEQ + rr]     = acc[mt][nt][1];
                op[rr + 8]       = acc[mt][nt][2];
                op[SEQ + rr + 8] = acc[mt][nt][3];
            }
        }
    }
}

// ---------------------------------------------------------------------------
extern "C" void kernel_launch(void* const* d_in, const int* in_sizes, int n_in,
                              void* d_out, int out_size) {
    const float* x     = (const float*)d_in[0];
    const float* fb1   = (const float*)d_in[1];
    const float* fband = (const float*)d_in[2];
    float* out = (float*)d_out;

    cudaFuncSetAttribute(conv_kernel,
                         cudaFuncAttributeMaxDynamicSharedMemorySize, SMEM_TOTAL);

    gen_filters_kernel<<<NF, 128>>>(fb1, fband);
    conv_kernel<<<GRID, NTHREADS, SMEM_TOTAL>>>(x, out);
}